// round 1
// baseline (speedup 1.0000x reference)
#include <cuda_runtime.h>
#include <cuda_bf16.h>

// Problem constants (fixed by the dataset)
#define BATCH 1024
#define SEQ   512
#define HID   64      // H
#define GATES 256     // 4H

#define NR    8       // batch rows per CTA
#define NCTA  (BATCH / NR)   // 128 CTAs
#define NTHR  256

struct Smem {
    // weights, transposed to [k][g] so gate-dim reads are coalesced
    float W1t[HID][GATES];        // W_hh1^T             64 KB
    float W2t[2 * HID][GATES];    // [W_ih2 ; W_hh2]^T  128 KB
    float gates[NR][GATES];       //                      8 KB
    float hcat[NR][2 * HID];      // [h1 ; h2] per row    4 KB
    float c1[NR][HID];            //                      2 KB
    float c2[NR][HID];            //                      2 KB
    float wih1[GATES];
    float bias1[GATES];           // b_ih1 + b_hh1
    float bias2[GATES];
    float wlin[HID];
    float xbuf[NR];
    float blin;
};

__device__ __forceinline__ float sig_f(float v) {
    // 1/(1+e^-v); e=inf -> 0, e=0 -> 1 (no NaN)
    float e = __expf(-v);
    return __fdividef(1.0f, 1.0f + e);
}
__device__ __forceinline__ float tanh_f(float v) {
    // 1 - 2/(1+e^{2v}); saturates cleanly to +-1
    float e = __expf(2.0f * v);
    return 1.0f - __fdividef(2.0f, 1.0f + e);
}

__device__ __forceinline__ void fma8(float h0, float h1, float h2, float h3, float2 w,
                                     float& a00, float& a01, float& a10, float& a11,
                                     float& a20, float& a21, float& a30, float& a31) {
    a00 = fmaf(h0, w.x, a00); a01 = fmaf(h0, w.y, a01);
    a10 = fmaf(h1, w.x, a10); a11 = fmaf(h1, w.y, a11);
    a20 = fmaf(h2, w.x, a20); a21 = fmaf(h2, w.y, a21);
    a30 = fmaf(h3, w.x, a30); a31 = fmaf(h3, w.y, a31);
}

// Accumulate a [4 rows x 2 gates] tile over K from Wt[k][g0..g0+1] and 4 h rows.
template <int K>
__device__ __forceinline__ void gemm_acc(const float (*Wt)[GATES],
                                         const float* hr0, const float* hr1,
                                         const float* hr2, const float* hr3, int g0,
                                         float& a00, float& a01, float& a10, float& a11,
                                         float& a20, float& a21, float& a30, float& a31) {
#pragma unroll
    for (int kk = 0; kk < K; kk += 4) {
        const float4 h0 = *reinterpret_cast<const float4*>(hr0 + kk);  // warp-broadcast
        const float4 h1 = *reinterpret_cast<const float4*>(hr1 + kk);
        const float4 h2 = *reinterpret_cast<const float4*>(hr2 + kk);
        const float4 h3 = *reinterpret_cast<const float4*>(hr3 + kk);
        float2 w;
        w = *reinterpret_cast<const float2*>(&Wt[kk + 0][g0]);
        fma8(h0.x, h1.x, h2.x, h3.x, w, a00, a01, a10, a11, a20, a21, a30, a31);
        w = *reinterpret_cast<const float2*>(&Wt[kk + 1][g0]);
        fma8(h0.y, h1.y, h2.y, h3.y, w, a00, a01, a10, a11, a20, a21, a30, a31);
        w = *reinterpret_cast<const float2*>(&Wt[kk + 2][g0]);
        fma8(h0.z, h1.z, h2.z, h3.z, w, a00, a01, a10, a11, a20, a21, a30, a31);
        w = *reinterpret_cast<const float2*>(&Wt[kk + 3][g0]);
        fma8(h0.w, h1.w, h2.w, h3.w, w, a00, a01, a10, a11, a20, a21, a30, a31);
    }
}

__global__ void __launch_bounds__(NTHR, 1)
lstm_persistent_kernel(const float* __restrict__ x,
                       const float* __restrict__ Wih1, const float* __restrict__ Whh1,
                       const float* __restrict__ bih1, const float* __restrict__ bhh1,
                       const float* __restrict__ Wih2, const float* __restrict__ Whh2,
                       const float* __restrict__ bih2, const float* __restrict__ bhh2,
                       const float* __restrict__ Wlin, const float* __restrict__ blin,
                       float* __restrict__ out) {
    extern __shared__ char smem_raw[];
    Smem& sm = *reinterpret_cast<Smem*>(smem_raw);

    const int tid  = threadIdx.x;
    const int wid  = tid >> 5;
    const int lane = tid & 31;
    const int row0 = blockIdx.x * NR;

    // ---- one-time staging ----
    // W_hh1 (256x64 row-major) -> W1t[k][g]
    for (int i = tid; i < GATES * HID; i += NTHR) {
        int g = i / HID, k = i % HID;
        sm.W1t[k][g] = Whh1[i];
    }
    // W_ih2 / W_hh2 -> W2t[k][g], k<64 from ih2, k>=64 from hh2
    for (int i = tid; i < GATES * HID; i += NTHR) {
        int g = i / HID, k = i % HID;
        sm.W2t[k][g]       = Wih2[i];
        sm.W2t[HID + k][g] = Whh2[i];
    }
    for (int i = tid; i < GATES; i += NTHR) {
        sm.wih1[i]  = Wih1[i];
        sm.bias1[i] = bih1[i] + bhh1[i];
        sm.bias2[i] = bih2[i] + bhh2[i];
    }
    if (tid < HID) sm.wlin[tid] = Wlin[tid];
    if (tid == 0)  sm.blin = blin[0];
    // zero state
    for (int i = tid; i < NR * 2 * HID; i += NTHR)
        reinterpret_cast<float*>(sm.hcat)[i] = 0.0f;
    for (int i = tid; i < NR * HID; i += NTHR) {
        reinterpret_cast<float*>(sm.c1)[i] = 0.0f;
        reinterpret_cast<float*>(sm.c2)[i] = 0.0f;
    }
    if (tid < NR) sm.xbuf[tid] = x[(row0 + tid) * SEQ + 0];
    __syncthreads();

    // compute-phase mapping: warp -> (row group of 4, gate slice of 64)
    const int rg    = wid >> 2;          // 0..1
    const int gs    = wid & 3;           // 0..3
    const int g0    = gs * 64 + lane * 2;
    const int rbase = rg * 4;
    const float* hr0 = &sm.hcat[rbase + 0][0];
    const float* hr1 = &sm.hcat[rbase + 1][0];
    const float* hr2 = &sm.hcat[rbase + 2][0];
    const float* hr3 = &sm.hcat[rbase + 3][0];

    // activation-phase mapping: warp -> row, lane -> cell j and j+32
    const int ar = wid;      // row
    const int aj = lane;

    for (int t = 0; t < SEQ; t++) {
        // ===== layer 1: gates1 = x*wih1 + bias1 + W_hh1 h1 =====
        float a00, a01, a10, a11, a20, a21, a30, a31;
        {
            float w0 = sm.wih1[g0], w1 = sm.wih1[g0 + 1];
            float b0 = sm.bias1[g0], b1 = sm.bias1[g0 + 1];
            float x0 = sm.xbuf[rbase + 0], x1 = sm.xbuf[rbase + 1];
            float x2 = sm.xbuf[rbase + 2], x3 = sm.xbuf[rbase + 3];
            a00 = fmaf(x0, w0, b0); a01 = fmaf(x0, w1, b1);
            a10 = fmaf(x1, w0, b0); a11 = fmaf(x1, w1, b1);
            a20 = fmaf(x2, w0, b0); a21 = fmaf(x2, w1, b1);
            a30 = fmaf(x3, w0, b0); a31 = fmaf(x3, w1, b1);
        }
        gemm_acc<HID>(sm.W1t, hr0, hr1, hr2, hr3, g0,
                      a00, a01, a10, a11, a20, a21, a30, a31);
        *reinterpret_cast<float2*>(&sm.gates[rbase + 0][g0]) = make_float2(a00, a01);
        *reinterpret_cast<float2*>(&sm.gates[rbase + 1][g0]) = make_float2(a10, a11);
        *reinterpret_cast<float2*>(&sm.gates[rbase + 2][g0]) = make_float2(a20, a21);
        *reinterpret_cast<float2*>(&sm.gates[rbase + 3][g0]) = make_float2(a30, a31);
        __syncthreads();

        // ===== activation 1 -> h1 (hcat[:,0:64]), c1 =====
        {
            float gi = sm.gates[ar][aj],       gf = sm.gates[ar][64 + aj];
            float gg = sm.gates[ar][128 + aj], go = sm.gates[ar][192 + aj];
            float c  = sig_f(gf) * sm.c1[ar][aj] + sig_f(gi) * tanh_f(gg);
            sm.c1[ar][aj]  = c;
            sm.hcat[ar][aj] = sig_f(go) * tanh_f(c);

            int j2 = aj + 32;
            gi = sm.gates[ar][j2];       gf = sm.gates[ar][64 + j2];
            gg = sm.gates[ar][128 + j2]; go = sm.gates[ar][192 + j2];
            c  = sig_f(gf) * sm.c1[ar][j2] + sig_f(gi) * tanh_f(gg);
            sm.c1[ar][j2]   = c;
            sm.hcat[ar][j2] = sig_f(go) * tanh_f(c);
        }
        __syncthreads();

        // ===== layer 2: gates2 = bias2 + [Wih2|Whh2] [h1;h2] =====
        {
            float b0 = sm.bias2[g0], b1 = sm.bias2[g0 + 1];
            a00 = b0; a01 = b1; a10 = b0; a11 = b1;
            a20 = b0; a21 = b1; a30 = b0; a31 = b1;
        }
        gemm_acc<2 * HID>(sm.W2t, hr0, hr1, hr2, hr3, g0,
                          a00, a01, a10, a11, a20, a21, a30, a31);
        *reinterpret_cast<float2*>(&sm.gates[rbase + 0][g0]) = make_float2(a00, a01);
        *reinterpret_cast<float2*>(&sm.gates[rbase + 1][g0]) = make_float2(a10, a11);
        *reinterpret_cast<float2*>(&sm.gates[rbase + 2][g0]) = make_float2(a20, a21);
        *reinterpret_cast<float2*>(&sm.gates[rbase + 3][g0]) = make_float2(a30, a31);
        __syncthreads();

        // ===== activation 2 -> h2 (hcat[:,64:128]), c2, output =====
        {
            float gi = sm.gates[ar][aj],       gf = sm.gates[ar][64 + aj];
            float gg = sm.gates[ar][128 + aj], go = sm.gates[ar][192 + aj];
            float c  = sig_f(gf) * sm.c2[ar][aj] + sig_f(gi) * tanh_f(gg);
            sm.c2[ar][aj] = c;
            float h2a = sig_f(go) * tanh_f(c);
            sm.hcat[ar][HID + aj] = h2a;

            int j2 = aj + 32;
            gi = sm.gates[ar][j2];       gf = sm.gates[ar][64 + j2];
            gg = sm.gates[ar][128 + j2]; go = sm.gates[ar][192 + j2];
            c  = sig_f(gf) * sm.c2[ar][j2] + sig_f(gi) * tanh_f(gg);
            sm.c2[ar][j2] = c;
            float h2b = sig_f(go) * tanh_f(c);
            sm.hcat[ar][HID + j2] = h2b;

            // out[row][t] = wlin . h2 + blin  (warp-reduce over 64 cells)
            float p = sm.wlin[aj] * h2a + sm.wlin[j2] * h2b;
#pragma unroll
            for (int off = 16; off > 0; off >>= 1)
                p += __shfl_xor_sync(0xffffffffu, p, off);
            if (lane == 0)
                out[(row0 + ar) * SEQ + t] = p + sm.blin;
        }
        // prefetch next x
        if (tid < NR && (t + 1) < SEQ)
            sm.xbuf[tid] = x[(row0 + tid) * SEQ + t + 1];
        __syncthreads();
    }
}

extern "C" void kernel_launch(void* const* d_in, const int* in_sizes, int n_in,
                              void* d_out, int out_size) {
    const float* x     = (const float*)d_in[0];
    const float* Wih1  = (const float*)d_in[1];
    const float* Whh1  = (const float*)d_in[2];
    const float* bih1  = (const float*)d_in[3];
    const float* bhh1  = (const float*)d_in[4];
    const float* Wih2  = (const float*)d_in[5];
    const float* Whh2  = (const float*)d_in[6];
    const float* bih2  = (const float*)d_in[7];
    const float* bhh2  = (const float*)d_in[8];
    const float* Wlin  = (const float*)d_in[9];
    const float* blin  = (const float*)d_in[10];
    float* out = (float*)d_out;

    (void)in_sizes; (void)n_in; (void)out_size;

    cudaFuncSetAttribute(lstm_persistent_kernel,
                         cudaFuncAttributeMaxDynamicSharedMemorySize,
                         (int)sizeof(Smem));
    lstm_persistent_kernel<<<NCTA, NTHR, sizeof(Smem)>>>(
        x, Wih1, Whh1, bih1, bhh1, Wih2, Whh2, bih2, bhh2, Wlin, blin, out);
}

// round 2
// speedup vs baseline: 1.0393x; 1.0393x over previous
#include <cuda_runtime.h>
#include <cuda_bf16.h>

#define BATCH 1024
#define SEQ   512
#define HID   64
#define GATES 256
#define NR    8
#define NCTA  (BATCH / NR)   // 128
#define NTHR  128            // 4 warps

typedef unsigned long long ull;

struct __align__(16) Smem {
    // Weights transposed + gate-interleaved: Ws[k][j*4 + hq] = W[gate(j,hq)][k]
    // gate(j,hq) = j + 64*hq  (hq: 0=i,1=f,2=g,3=o)
    float W1[HID][GATES];        //  64 KB (W_hh1)
    float W2[2 * HID][GATES];    // 128 KB ([W_ih2 ; W_hh2])
    float hb[2][2 * HID][NR];    //   8 KB  [buf][k][row]; k<64: h1, k>=64: h2
    float wih1v[GATES];          // gate-interleaved
    float b1v[GATES];
    float b2v[GATES];
    float wlin[HID];
    float xs[2][NR];
    float outp[8][4];            // [warp*2+half][i]  (row = half*4+i)
    float blin;
};

__device__ __forceinline__ ull pk2(float lo, float hi) {
    ull r; asm("mov.b64 %0, {%1, %2};" : "=l"(r) : "f"(lo), "f"(hi)); return r;
}
__device__ __forceinline__ void unpk(ull v, float& lo, float& hi) {
    asm("mov.b64 {%0, %1}, %2;" : "=f"(lo), "=f"(hi) : "l"(v));
}
__device__ __forceinline__ void fma2(ull& d, ull a, ull b) {
    asm("fma.rn.f32x2 %0, %1, %2, %0;" : "+l"(d) : "l"(a), "l"(b));
}

__device__ __forceinline__ float sigf(float v) {
    float e = __expf(-v);
    return __fdividef(1.0f, 1.0f + e);
}
__device__ __forceinline__ float tanhf_(float v) {
    float e = __expf(2.0f * v);
    return 1.0f - __fdividef(2.0f, 1.0f + e);
}

// 16 consecutive k-steps: acc[q][rp] += h[k][2rp..2rp+1] * w[k][gate q]
__device__ __forceinline__ void gemm16(const float* __restrict__ wp,
                                       const float* __restrict__ hp,
                                       ull acc[2][4]) {
#pragma unroll
    for (int kk = 0; kk < 16; kk++) {
        ulonglong2 hA = *reinterpret_cast<const ulonglong2*>(hp + kk * 8);      // rows {0,1},{2,3}
        ulonglong2 hB = *reinterpret_cast<const ulonglong2*>(hp + kk * 8 + 4);  // rows {4,5},{6,7}
        float2 wv = *reinterpret_cast<const float2*>(wp + kk * GATES);
        ull w0 = pk2(wv.x, wv.x);
        ull w1 = pk2(wv.y, wv.y);
        fma2(acc[0][0], hA.x, w0); fma2(acc[0][1], hA.y, w0);
        fma2(acc[0][2], hB.x, w0); fma2(acc[0][3], hB.y, w0);
        fma2(acc[1][0], hA.x, w1); fma2(acc[1][1], hA.y, w1);
        fma2(acc[1][2], hB.x, w1); fma2(acc[1][3], hB.y, w1);
    }
}

// Exchange gates with partner lane (xor 16), run LSTM cell for this thread's 4 rows.
__device__ __forceinline__ void do_act(ull acc[2][4], int half, float cst[4], float h[4]) {
    // send the row-pairs the partner keeps; receive my row-pairs of the partner's gates
    ull send0 = half ? acc[0][0] : acc[0][2];
    ull send1 = half ? acc[0][1] : acc[0][3];
    ull send2 = half ? acc[1][0] : acc[1][2];
    ull send3 = half ? acc[1][1] : acc[1][3];
    ull recv0 = __shfl_xor_sync(0xffffffffu, send0, 16);
    ull recv1 = __shfl_xor_sync(0xffffffffu, send1, 16);
    ull recv2 = __shfl_xor_sync(0xffffffffu, send2, 16);
    ull recv3 = __shfl_xor_sync(0xffffffffu, send3, 16);
    ull keep0 = half ? acc[0][2] : acc[0][0];
    ull keep1 = half ? acc[0][3] : acc[0][1];
    ull keep2 = half ? acc[1][2] : acc[1][0];
    ull keep3 = half ? acc[1][3] : acc[1][1];
    // half0 owns (i,f), receives (g,o); half1 owns (g,o), receives (i,f)
    ull iA = half ? recv0 : keep0, iB = half ? recv1 : keep1;
    ull fA = half ? recv2 : keep2, fB = half ? recv3 : keep3;
    ull gA = half ? keep0 : recv0, gB = half ? keep1 : recv1;
    ull oA = half ? keep2 : recv2, oB = half ? keep3 : recv3;
    float gi[4], gf[4], gg[4], go[4];
    unpk(iA, gi[0], gi[1]); unpk(iB, gi[2], gi[3]);
    unpk(fA, gf[0], gf[1]); unpk(fB, gf[2], gf[3]);
    unpk(gA, gg[0], gg[1]); unpk(gB, gg[2], gg[3]);
    unpk(oA, go[0], go[1]); unpk(oB, go[2], go[3]);
#pragma unroll
    for (int i = 0; i < 4; i++) {
        float c = sigf(gf[i]) * cst[i] + sigf(gi[i]) * tanhf_(gg[i]);
        cst[i] = c;
        h[i] = sigf(go[i]) * tanhf_(c);
    }
}

__global__ void __launch_bounds__(NTHR, 1)
lstm_persistent_kernel(const float* __restrict__ x,
                       const float* __restrict__ Wih1, const float* __restrict__ Whh1,
                       const float* __restrict__ bih1, const float* __restrict__ bhh1,
                       const float* __restrict__ Wih2, const float* __restrict__ Whh2,
                       const float* __restrict__ bih2, const float* __restrict__ bhh2,
                       const float* __restrict__ Wlin, const float* __restrict__ blin,
                       float* __restrict__ out) {
    extern __shared__ char smem_raw[];
    Smem& sm = *reinterpret_cast<Smem*>(smem_raw);

    const int tid  = threadIdx.x;
    const int wid  = tid >> 5;
    const int lane = tid & 31;
    const int row0 = blockIdx.x * NR;

    // ---- one-time staging (transpose + gate-interleave) ----
    for (int i = tid; i < GATES * HID; i += NTHR) {
        int g = i >> 6, k = i & 63;
        int col = (g & 63) * 4 + (g >> 6);     // j*4 + hq
        sm.W1[k][col]      = Whh1[i];
        sm.W2[k][col]      = Wih2[i];
        sm.W2[64 + k][col] = Whh2[i];
    }
    for (int i = tid; i < GATES; i += NTHR) {
        int col = (i & 63) * 4 + (i >> 6);
        sm.wih1v[col] = Wih1[i];
        sm.b1v[col]   = bih1[i] + bhh1[i];
        sm.b2v[col]   = bih2[i] + bhh2[i];
    }
    if (tid < HID) sm.wlin[tid] = Wlin[tid];
    if (tid == 0)  sm.blin = blin[0];
    for (int i = tid; i < 2 * 2 * HID * NR; i += NTHR)
        reinterpret_cast<float*>(sm.hb)[i] = 0.0f;
    if (tid < NR) sm.xs[0][tid] = x[(row0 + tid) * SEQ + 0];
    __syncthreads();

    // thread -> (cell j, gate-half); owns its 2 gates for all 8 rows in the GEMM,
    // and cell state for rows [half*4, half*4+4) in the activation.
    const int j    = (wid << 4) | (lane & 15);
    const int half = lane >> 4;
    const int j4   = j * 4 + half * 2;

    float c1v[4] = {0.f, 0.f, 0.f, 0.f};
    float c2v[4] = {0.f, 0.f, 0.f, 0.f};

    for (int t = 0; t < SEQ; t++) {
        const int cur = t & 1, nxt = cur ^ 1;

        // finalize out[t-1] (outp written before last sync; overwritten only after next sync)
        if (t > 0 && tid < NR) {
            float s = sm.blin
                    + sm.outp[0 + (tid >> 2)][tid & 3] + sm.outp[2 + (tid >> 2)][tid & 3]
                    + sm.outp[4 + (tid >> 2)][tid & 3] + sm.outp[6 + (tid >> 2)][tid & 3];
            out[(row0 + tid) * SEQ + (t - 1)] = s;
        }

        // ===== layer 1: acc = bias1 + x*wih1 + W_hh1 h1(t-1) =====
        ull acc[2][4];
        {
            float2 wiv = *reinterpret_cast<const float2*>(&sm.wih1v[j4]);
            float2 bv  = *reinterpret_cast<const float2*>(&sm.b1v[j4]);
            ull w0 = pk2(wiv.x, wiv.x), w1 = pk2(wiv.y, wiv.y);
            ull b0 = pk2(bv.x, bv.x),   b1 = pk2(bv.y, bv.y);
            const float* xp = sm.xs[cur];
            ulonglong2 xA = *reinterpret_cast<const ulonglong2*>(xp);
            ulonglong2 xB = *reinterpret_cast<const ulonglong2*>(xp + 4);
            acc[0][0] = b0; acc[0][1] = b0; acc[0][2] = b0; acc[0][3] = b0;
            acc[1][0] = b1; acc[1][1] = b1; acc[1][2] = b1; acc[1][3] = b1;
            fma2(acc[0][0], xA.x, w0); fma2(acc[0][1], xA.y, w0);
            fma2(acc[0][2], xB.x, w0); fma2(acc[0][3], xB.y, w0);
            fma2(acc[1][0], xA.x, w1); fma2(acc[1][1], xA.y, w1);
            fma2(acc[1][2], xB.x, w1); fma2(acc[1][3], xB.y, w1);
        }
        {
            const float* wp = &sm.W1[0][j4];
            const float* hp = &sm.hb[cur][0][0];
#pragma unroll 1
            for (int kb = 0; kb < 4; kb++) {
                gemm16(wp, hp, acc);
                wp += 16 * GATES; hp += 16 * NR;
            }
        }
        // activation 1 -> h1(t) into hb[nxt][0..63]
        {
            float h[4];
            do_act(acc, half, c1v, h);
            float* dst = &sm.hb[nxt][j][half * 4];
            *reinterpret_cast<ull*>(dst)     = pk2(h[0], h[1]);
            *reinterpret_cast<ull*>(dst + 2) = pk2(h[2], h[3]);
        }
        __syncthreads();

        // ===== layer 2: acc = bias2 + W_ih2 h1(t) + W_hh2 h2(t-1) =====
        {
            float2 bv = *reinterpret_cast<const float2*>(&sm.b2v[j4]);
            ull b0 = pk2(bv.x, bv.x), b1 = pk2(bv.y, bv.y);
            acc[0][0] = b0; acc[0][1] = b0; acc[0][2] = b0; acc[0][3] = b0;
            acc[1][0] = b1; acc[1][1] = b1; acc[1][2] = b1; acc[1][3] = b1;
        }
        {
            const float* wp = &sm.W2[0][j4];
            const float* hp = &sm.hb[nxt][0][0];          // new h1
#pragma unroll 1
            for (int kb = 0; kb < 4; kb++) {
                gemm16(wp, hp, acc);
                wp += 16 * GATES; hp += 16 * NR;
            }
            wp = &sm.W2[64][j4];
            hp = &sm.hb[cur][64][0];                       // old h2
#pragma unroll 1
            for (int kb = 0; kb < 4; kb++) {
                gemm16(wp, hp, acc);
                wp += 16 * GATES; hp += 16 * NR;
            }
        }
        // activation 2 -> h2(t) into hb[nxt][64..127] + output partials
        {
            float h[4];
            do_act(acc, half, c2v, h);
            float* dst = &sm.hb[nxt][64 + j][half * 4];
            *reinterpret_cast<ull*>(dst)     = pk2(h[0], h[1]);
            *reinterpret_cast<ull*>(dst + 2) = pk2(h[2], h[3]);

            float wl = sm.wlin[j];
            float p0 = wl * h[0], p1 = wl * h[1], p2 = wl * h[2], p3 = wl * h[3];
#pragma unroll
            for (int off = 8; off > 0; off >>= 1) {
                p0 += __shfl_xor_sync(0xffffffffu, p0, off);
                p1 += __shfl_xor_sync(0xffffffffu, p1, off);
                p2 += __shfl_xor_sync(0xffffffffu, p2, off);
                p3 += __shfl_xor_sync(0xffffffffu, p3, off);
            }
            if ((lane & 15) == 0) {
                float* op = sm.outp[wid * 2 + half];
                op[0] = p0; op[1] = p1; op[2] = p2; op[3] = p3;
            }
        }
        // prefetch x for t+1
        if (tid < NR && (t + 1) < SEQ)
            sm.xs[nxt][tid] = x[(row0 + tid) * SEQ + t + 1];
        __syncthreads();
    }

    // finalize out[SEQ-1]
    if (tid < NR) {
        float s = sm.blin
                + sm.outp[0 + (tid >> 2)][tid & 3] + sm.outp[2 + (tid >> 2)][tid & 3]
                + sm.outp[4 + (tid >> 2)][tid & 3] + sm.outp[6 + (tid >> 2)][tid & 3];
        out[(row0 + tid) * SEQ + (SEQ - 1)] = s;
    }
}

extern "C" void kernel_launch(void* const* d_in, const int* in_sizes, int n_in,
                              void* d_out, int out_size) {
    const float* x     = (const float*)d_in[0];
    const float* Wih1  = (const float*)d_in[1];
    const float* Whh1  = (const float*)d_in[2];
    const float* bih1  = (const float*)d_in[3];
    const float* bhh1  = (const float*)d_in[4];
    const float* Wih2  = (const float*)d_in[5];
    const float* Whh2  = (const float*)d_in[6];
    const float* bih2  = (const float*)d_in[7];
    const float* bhh2  = (const float*)d_in[8];
    const float* Wlin  = (const float*)d_in[9];
    const float* blin  = (const float*)d_in[10];
    float* out = (float*)d_out;

    (void)in_sizes; (void)n_in; (void)out_size;

    cudaFuncSetAttribute(lstm_persistent_kernel,
                         cudaFuncAttributeMaxDynamicSharedMemorySize,
                         (int)sizeof(Smem));
    lstm_persistent_kernel<<<NCTA, NTHR, sizeof(Smem)>>>(
        x, Wih1, Whh1, bih1, bhh1, Wih2, Whh2, bih2, bhh2, Wlin, blin, out);
}

// round 3
// speedup vs baseline: 1.2357x; 1.1890x over previous
#include <cuda_runtime.h>
#include <cuda_bf16.h>

#define BATCH 1024
#define SEQ   512
#define HID   64
#define GATES 256
#define NR    8
#define NCTA  (BATCH / NR)   // 128
#define NTHR  256            // 8 warps, 2 k-split groups

typedef unsigned long long ull;

struct __align__(16) Smem {
    // Weights transposed; column = owning-thread slot (conflict-free LDS):
    //   gate g: j=g&63, hq=g>>6; wq=j>>4, ln=(j&15)|((hq>>1)<<4), q=hq&1
    //   col = ((wq<<5)|ln)*2 + q
    float W1[HID][GATES];          //  64 KB (W_hh1)
    float W2[2 * HID][GATES];      // 128 KB ([W_ih2 ; W_hh2])
    float hb[2][2 * HID][NR];      //   8 KB  [buf][k][row]; k<64: h1, else h2
    ulonglong2 pexA[2][4][32];     //   4 KB  k-split partial exchange
    ulonglong2 pexB[2][4][32];     //   4 KB
    float wih1v[GATES];
    float b1v[GATES];
    float b2v[GATES];
    float wlin[HID];
    float xs[2][NR];
    float outp[8][2][2];           // [wid][half][e]
    float blin;
};

__device__ __forceinline__ ull pk2(float lo, float hi) {
    ull r; asm("mov.b64 %0, {%1, %2};" : "=l"(r) : "f"(lo), "f"(hi)); return r;
}
__device__ __forceinline__ void unpk(ull v, float& lo, float& hi) {
    asm("mov.b64 {%0, %1}, %2;" : "=f"(lo), "=f"(hi) : "l"(v));
}
__device__ __forceinline__ void fma2(ull& d, ull a, ull b) {
    asm("fma.rn.f32x2 %0, %1, %2, %0;" : "+l"(d) : "l"(a), "l"(b));
}
__device__ __forceinline__ ull add2(ull a, ull b) {
    ull d; asm("add.rn.f32x2 %0, %1, %2;" : "=l"(d) : "l"(a), "l"(b)); return d;
}

__device__ __forceinline__ float sigf(float v) {
    float e = __expf(-v);
    return __fdividef(1.0f, 1.0f + e);
}
__device__ __forceinline__ float tanhf_(float v) {
    float e = __expf(2.0f * v);
    return 1.0f - __fdividef(2.0f, 1.0f + e);
}

// 16 k-steps: acc[q][rp] += h[k][rows 2rp,2rp+1] * w[k][col+q]
__device__ __forceinline__ void gemm16(const float* __restrict__ wp,
                                       const float* __restrict__ hp,
                                       ull acc[2][4]) {
#pragma unroll
    for (int kk = 0; kk < 16; kk++) {
        ulonglong2 hA = *reinterpret_cast<const ulonglong2*>(hp + kk * 8);      // rows {0,1},{2,3}
        ulonglong2 hB = *reinterpret_cast<const ulonglong2*>(hp + kk * 8 + 4);  // rows {4,5},{6,7}
        float2 wv = *reinterpret_cast<const float2*>(wp + kk * GATES);
        ull w0 = pk2(wv.x, wv.x);
        ull w1 = pk2(wv.y, wv.y);
        fma2(acc[0][0], hA.x, w0); fma2(acc[0][1], hA.y, w0);
        fma2(acc[0][2], hB.x, w0); fma2(acc[0][3], hB.y, w0);
        fma2(acc[1][0], hA.x, w1); fma2(acc[1][1], hA.y, w1);
        fma2(acc[1][2], hB.x, w1); fma2(acc[1][3], hB.y, w1);
    }
}

// k-split reduce + gate exchange + LSTM cell for 2 rows.
// On entry acc holds this group's partial for all 8 rows; other group's partial
// for this group's row quad is in pex[grp^1]. Returns h for rows rbase,rbase+1.
__device__ __forceinline__ void reduce_act(Smem& sm, ull acc[2][4], int grp, int wq,
                                           int lane, int half, float cst[2], float h[2]) {
    ulonglong2 ra = sm.pexA[grp ^ 1][wq][lane];
    ulonglong2 rb = sm.pexB[grp ^ 1][wq][lane];
    ull kq00, kq01, kq10, kq11;   // kq[q][pair-in-quad]
    if (grp == 0) {
        kq00 = add2(acc[0][0], ra.x); kq01 = add2(acc[0][1], ra.y);
        kq10 = add2(acc[1][0], rb.x); kq11 = add2(acc[1][1], rb.y);
    } else {
        kq00 = add2(acc[0][2], ra.x); kq01 = add2(acc[0][3], ra.y);
        kq10 = add2(acc[1][2], rb.x); kq11 = add2(acc[1][3], rb.y);
    }
    // trade gates across half-warps: keep pair p=half, send p=1-half
    ull send0 = half ? kq00 : kq01;
    ull send1 = half ? kq10 : kq11;
    ull recv0 = __shfl_xor_sync(0xffffffffu, send0, 16);
    ull recv1 = __shfl_xor_sync(0xffffffffu, send1, 16);
    ull keep0 = half ? kq01 : kq00;
    ull keep1 = half ? kq11 : kq10;
    ull iP = half ? recv0 : keep0;
    ull fP = half ? recv1 : keep1;
    ull gP = half ? keep0 : recv0;
    ull oP = half ? keep1 : recv1;
    float gi0, gi1, gf0, gf1, gg0, gg1, go0, go1;
    unpk(iP, gi0, gi1); unpk(fP, gf0, gf1);
    unpk(gP, gg0, gg1); unpk(oP, go0, go1);
    float c0 = sigf(gf0) * cst[0] + sigf(gi0) * tanhf_(gg0);
    float c1 = sigf(gf1) * cst[1] + sigf(gi1) * tanhf_(gg1);
    cst[0] = c0; cst[1] = c1;
    h[0] = sigf(go0) * tanhf_(c0);
    h[1] = sigf(go1) * tanhf_(c1);
}

__device__ __forceinline__ void store_partials(Smem& sm, ull acc[2][4], int grp,
                                               int wq, int lane) {
    if (grp == 0) {   // send rows 4-7
        sm.pexA[0][wq][lane] = make_ulonglong2(acc[0][2], acc[0][3]);
        sm.pexB[0][wq][lane] = make_ulonglong2(acc[1][2], acc[1][3]);
    } else {          // send rows 0-3
        sm.pexA[1][wq][lane] = make_ulonglong2(acc[0][0], acc[0][1]);
        sm.pexB[1][wq][lane] = make_ulonglong2(acc[1][0], acc[1][1]);
    }
}

__global__ void __launch_bounds__(NTHR, 1)
lstm_persistent_kernel(const float* __restrict__ x,
                       const float* __restrict__ Wih1, const float* __restrict__ Whh1,
                       const float* __restrict__ bih1, const float* __restrict__ bhh1,
                       const float* __restrict__ Wih2, const float* __restrict__ Whh2,
                       const float* __restrict__ bih2, const float* __restrict__ bhh2,
                       const float* __restrict__ Wlin, const float* __restrict__ blin,
                       float* __restrict__ out) {
    extern __shared__ char smem_raw[];
    Smem& sm = *reinterpret_cast<Smem*>(smem_raw);

    const int tid  = threadIdx.x;
    const int wid  = tid >> 5;
    const int lane = tid & 31;
    const int row0 = blockIdx.x * NR;

    // ---- one-time staging ----
    for (int i = tid; i < GATES * HID; i += NTHR) {
        int g = i >> 6, k = i & 63;
        int jj = g & 63, hq = g >> 6;
        int col = (((jj >> 4) << 5) | ((jj & 15) | ((hq >> 1) << 4))) * 2 + (hq & 1);
        sm.W1[k][col]      = Whh1[i];
        sm.W2[k][col]      = Wih2[i];
        sm.W2[64 + k][col] = Whh2[i];
    }
    for (int g = tid; g < GATES; g += NTHR) {
        int jj = g & 63, hq = g >> 6;
        int col = (((jj >> 4) << 5) | ((jj & 15) | ((hq >> 1) << 4))) * 2 + (hq & 1);
        sm.wih1v[col] = Wih1[g];
        sm.b1v[col]   = bih1[g] + bhh1[g];
        sm.b2v[col]   = bih2[g] + bhh2[g];
    }
    if (tid < HID) sm.wlin[tid] = Wlin[tid];
    if (tid == 0)  sm.blin = blin[0];
    for (int i = tid; i < 2 * 2 * HID * NR; i += NTHR)
        reinterpret_cast<float*>(sm.hb)[i] = 0.0f;
    if (tid < NR) sm.xs[0][tid] = x[(row0 + tid) * SEQ + 0];
    __syncthreads();

    const int wq   = wid & 3;            // j block
    const int grp  = wid >> 2;           // k-split group / row quad
    const int half = lane >> 4;          // gate half: 0=(i,f) 1=(g,o)
    const int j    = (wq << 4) | (lane & 15);
    const int c2   = ((wq << 5) | lane) * 2;
    const int rbase = grp * 4 + half * 2;

    float c1v[2] = {0.f, 0.f};
    float c2v[2] = {0.f, 0.f};

    for (int t = 0; t < SEQ; t++) {
        const int cur = t & 1, nxt = cur ^ 1;

        // finalize out[t-1]
        if (t > 0 && tid < NR) {
            int gr = tid >> 2, hf = (tid >> 1) & 1, e = tid & 1;
            float s = sm.blin
                    + sm.outp[gr * 4 + 0][hf][e] + sm.outp[gr * 4 + 1][hf][e]
                    + sm.outp[gr * 4 + 2][hf][e] + sm.outp[gr * 4 + 3][hf][e];
            out[(row0 + tid) * SEQ + (t - 1)] = s;
        }

        // ===== layer 1: split K=64 over groups (32 each) =====
        ull acc[2][4];
        if (grp == 0) {
            float2 wiv = *reinterpret_cast<const float2*>(&sm.wih1v[c2]);
            float2 bv  = *reinterpret_cast<const float2*>(&sm.b1v[c2]);
            ull w0 = pk2(wiv.x, wiv.x), w1 = pk2(wiv.y, wiv.y);
            ull b0 = pk2(bv.x, bv.x),   b1 = pk2(bv.y, bv.y);
            const float* xp = sm.xs[cur];
            ulonglong2 xA = *reinterpret_cast<const ulonglong2*>(xp);
            ulonglong2 xB = *reinterpret_cast<const ulonglong2*>(xp + 4);
            acc[0][0] = b0; acc[0][1] = b0; acc[0][2] = b0; acc[0][3] = b0;
            acc[1][0] = b1; acc[1][1] = b1; acc[1][2] = b1; acc[1][3] = b1;
            fma2(acc[0][0], xA.x, w0); fma2(acc[0][1], xA.y, w0);
            fma2(acc[0][2], xB.x, w0); fma2(acc[0][3], xB.y, w0);
            fma2(acc[1][0], xA.x, w1); fma2(acc[1][1], xA.y, w1);
            fma2(acc[1][2], xB.x, w1); fma2(acc[1][3], xB.y, w1);
        } else {
#pragma unroll
            for (int q = 0; q < 2; q++)
#pragma unroll
                for (int r = 0; r < 4; r++) acc[q][r] = 0ull;
        }
        {
            const float* wp = &sm.W1[grp * 32][c2];
            const float* hp = &sm.hb[cur][grp * 32][0];
#pragma unroll 1
            for (int kb = 0; kb < 2; kb++) {
                gemm16(wp, hp, acc);
                wp += 16 * GATES; hp += 16 * NR;
            }
        }
        store_partials(sm, acc, grp, wq, lane);
        __syncthreads();
        {
            float h[2];
            reduce_act(sm, acc, grp, wq, lane, half, c1v, h);
            *reinterpret_cast<ull*>(&sm.hb[nxt][j][rbase]) = pk2(h[0], h[1]);
        }
        __syncthreads();

        // ===== layer 2: grp0 = W_ih2 * h1(t), grp1 = W_hh2 * h2(t-1) =====
        if (grp == 0) {
            float2 bv = *reinterpret_cast<const float2*>(&sm.b2v[c2]);
            ull b0 = pk2(bv.x, bv.x), b1 = pk2(bv.y, bv.y);
            acc[0][0] = b0; acc[0][1] = b0; acc[0][2] = b0; acc[0][3] = b0;
            acc[1][0] = b1; acc[1][1] = b1; acc[1][2] = b1; acc[1][3] = b1;
        } else {
#pragma unroll
            for (int q = 0; q < 2; q++)
#pragma unroll
                for (int r = 0; r < 4; r++) acc[q][r] = 0ull;
        }
        {
            const float* wp = &sm.W2[grp * 64][c2];
            const float* hp = grp ? &sm.hb[cur][64][0] : &sm.hb[nxt][0][0];
#pragma unroll 1
            for (int kb = 0; kb < 4; kb++) {
                gemm16(wp, hp, acc);
                wp += 16 * GATES; hp += 16 * NR;
            }
        }
        store_partials(sm, acc, grp, wq, lane);
        __syncthreads();
        {
            float h[2];
            reduce_act(sm, acc, grp, wq, lane, half, c2v, h);
            *reinterpret_cast<ull*>(&sm.hb[nxt][64 + j][rbase]) = pk2(h[0], h[1]);

            float wl = sm.wlin[j];
            float p0 = wl * h[0], p1 = wl * h[1];
#pragma unroll
            for (int off = 8; off > 0; off >>= 1) {
                p0 += __shfl_xor_sync(0xffffffffu, p0, off);
                p1 += __shfl_xor_sync(0xffffffffu, p1, off);
            }
            if ((lane & 15) == 0) {
                sm.outp[wid][half][0] = p0;
                sm.outp[wid][half][1] = p1;
            }
        }
        if (tid < NR && (t + 1) < SEQ)
            sm.xs[nxt][tid] = x[(row0 + tid) * SEQ + t + 1];
        __syncthreads();
    }

    if (tid < NR) {
        int gr = tid >> 2, hf = (tid >> 1) & 1, e = tid & 1;
        float s = sm.blin
                + sm.outp[gr * 4 + 0][hf][e] + sm.outp[gr * 4 + 1][hf][e]
                + sm.outp[gr * 4 + 2][hf][e] + sm.outp[gr * 4 + 3][hf][e];
        out[(row0 + tid) * SEQ + (SEQ - 1)] = s;
    }
}

extern "C" void kernel_launch(void* const* d_in, const int* in_sizes, int n_in,
                              void* d_out, int out_size) {
    const float* x     = (const float*)d_in[0];
    const float* Wih1  = (const float*)d_in[1];
    const float* Whh1  = (const float*)d_in[2];
    const float* bih1  = (const float*)d_in[3];
    const float* bhh1  = (const float*)d_in[4];
    const float* Wih2  = (const float*)d_in[5];
    const float* Whh2  = (const float*)d_in[6];
    const float* bih2  = (const float*)d_in[7];
    const float* bhh2  = (const float*)d_in[8];
    const float* Wlin  = (const float*)d_in[9];
    const float* blin  = (const float*)d_in[10];
    float* out = (float*)d_out;

    (void)in_sizes; (void)n_in; (void)out_size;

    cudaFuncSetAttribute(lstm_persistent_kernel,
                         cudaFuncAttributeMaxDynamicSharedMemorySize,
                         (int)sizeof(Smem));
    lstm_persistent_kernel<<<NCTA, NTHR, sizeof(Smem)>>>(
        x, Wih1, Whh1, bih1, bhh1, Wih2, Whh2, bih2, bhh2, Wlin, blin, out);
}